// round 8
// baseline (speedup 1.0000x reference)
#include <cuda_runtime.h>
#include <cuda_fp16.h>
#include <cuda_bf16.h>

// Problem constants
#define B_   32
#define N_   4096
#define DK_  128
#define H_   128
#define A_   128
#define CH_  16
#define TILE_ 256
#define GRID_ 512

// ---------------- scratch (device globals) ---------------------------------
// Interleaved fp16: per row idx, lane l owns halves [l*8..l*8+7] =
// {zfea[4l..4l+3], z[4l..4l+3]} -> one uint4 (16B) load per (row, lane).
__device__ __half g_zi[(size_t)B_*N_*256];   // 67MB
__device__ float g_s2[2][B_*DK_];      // double-buffered context (LSTM input)
__device__ float g_hbuf[2][B_*H_];     // double-buffered hidden state
__device__ float g_c[B_*H_];           // cell state
__device__ float g_xn[B_*2*H_];        // [h_new | c_new] per batch
__device__ float g_dec2[2][B_*A_];     // double-buffered dec_fea
__device__ float g_WxT[A_*2*H_];       // transposed W_x: [a][k]
__device__ float g_Sp2[2][B_*CH_];     // double-buffered softmax partials
__device__ float g_CTp2[2][B_*CH_*DK_]; // double-buffered context partials
__device__ float g_clp[GRID_];         // per-block closs partials (deterministic)
// dataflow counters (monotonic within a launch; reset by zfea launch)
__device__ unsigned g_cntA, g_cntB, g_cntC, g_cntS, g_cntDone;
__device__ unsigned g_cntSp[B_];

__device__ __forceinline__ float tanh_fast(float x) {
    float y; asm("tanh.approx.f32 %0, %1;" : "=f"(y) : "f"(x)); return y;
}
__device__ __forceinline__ float sigmoid_f(float x) {
    return 1.0f / (1.0f + __expf(-x));
}
__device__ __forceinline__ unsigned h2_to_u(__half2 h) {
    return *reinterpret_cast<unsigned*>(&h);
}
__device__ __forceinline__ float2 u_to_f2(unsigned u) {
    __half2 h = *reinterpret_cast<__half2*>(&u);
    return __half22float2(h);
}

// tid0 spins until *c >= tgt (monotonic counter). Caller must follow the last
// wait with acquire(): tid0 threadfence + syncthreads.
__device__ __forceinline__ void spin_ge(volatile unsigned* c, unsigned tgt) {
    if (threadIdx.x == 0) {
        int sp = 0;
        while (*c < tgt) { if (++sp > 128) __nanosleep(128); }
    }
}
__device__ __forceinline__ void acquire_fence() {
    if (threadIdx.x == 0) __threadfence();
    __syncthreads();
}
// release: all threads fence their writes, then tid0 bumps the counter
__device__ __forceinline__ void block_signal(unsigned* c) {
    __threadfence();
    __syncthreads();
    if (threadIdx.x == 0) atomicAdd(c, 1u);
}

// ---------------- one-time: zfea GEMM + init + counter reset ---------------
__global__ void zfea_kernel(const float* __restrict__ z, const float* __restrict__ Wz,
                            const float* __restrict__ battn,
                            const float* __restrict__ Wx,
                            const float* __restrict__ h0, const float* __restrict__ c0) {
    int t = threadIdx.x;
    int bid = blockIdx.x;

    // counter reset (block 0) — stream order guarantees visibility to persistent_kernel
    if (bid == 0) {
        if (t == 0) { g_cntA = 0; g_cntB = 0; g_cntC = 0; g_cntS = 0; g_cntDone = 0; }
        if (t < B_) g_cntSp[t] = 0;
    }
    // W_x transpose (blocks 0..127)
    if (bid < 128) {
        int i = bid*256 + t;
        int k = i >> 7, a = i & 127;
        g_WxT[a*(2*H_) + k] = Wx[k*A_ + a];
    }
    // state init (blocks 128..143)
    if (bid >= 128 && bid < 144) {
        int idx = (bid-128)*256 + t;
        g_s2[0][idx] = 0.0f;
        g_hbuf[0][idx] = h0[idx];
        g_c[idx] = c0[idx];
    }

    __shared__ float zs[64*DK_];
    int rowBase = bid * 64;
    const float* zsrc = z + (size_t)rowBase * DK_;
    #pragma unroll
    for (int k = 0; k < 32; k++) zs[t + k*256] = zsrc[t + k*256];
    __syncthreads();

    int tx = t & 31, ty = t >> 5;
    float acc[8][4];
    #pragma unroll
    for (int i = 0; i < 8; i++)
        #pragma unroll
        for (int c = 0; c < 4; c++) acc[i][c] = 0.0f;

    const float4* Wz4 = (const float4*)Wz;
    #pragma unroll 4
    for (int d = 0; d < DK_; d++) {
        float4 w = __ldg(&Wz4[d*32 + tx]);
        #pragma unroll
        for (int i = 0; i < 8; i++) {
            float zv = zs[(ty + 8*i)*DK_ + d];
            acc[i][0] = fmaf(zv, w.x, acc[i][0]);
            acc[i][1] = fmaf(zv, w.y, acc[i][1]);
            acc[i][2] = fmaf(zv, w.z, acc[i][2]);
            acc[i][3] = fmaf(zv, w.w, acc[i][3]);
        }
    }
    float4 bb = __ldg(&((const float4*)battn)[tx]);
    uint4* outp = (uint4*)g_zi;
    #pragma unroll
    for (int i = 0; i < 8; i++) {
        size_t r = rowBase + ty + 8*i;
        int lr = ty + 8*i;
        __half2 f0 = __floats2half2_rn(acc[i][0] + bb.x, acc[i][1] + bb.y);
        __half2 f1 = __floats2half2_rn(acc[i][2] + bb.z, acc[i][3] + bb.w);
        __half2 z0 = __floats2half2_rn(zs[lr*DK_ + tx*4],     zs[lr*DK_ + tx*4 + 1]);
        __half2 z1 = __floats2half2_rn(zs[lr*DK_ + tx*4 + 2], zs[lr*DK_ + tx*4 + 3]);
        uint4 pk;
        pk.x = h2_to_u(f0); pk.y = h2_to_u(f1);
        pk.z = h2_to_u(z0); pk.w = h2_to_u(z1);
        outp[r*32 + tx] = pk;
    }
}

// ---------------- persistent dataflow loop ---------------------------------
__global__ __launch_bounds__(256, 4) void persistent_kernel(
        float* __restrict__ out, int T, int out_size,
        const float* __restrict__ Wih, const float* __restrict__ Whh,
        const float* __restrict__ bih, const float* __restrict__ bhh,
        const float* __restrict__ mask,
        const float* __restrict__ wc, const float* __restrict__ v) {
    int bid = blockIdx.x;
    int tid = threadIdx.x;
    int warp = tid >> 5, lane = tid & 31;
    __shared__ float shm[136];

    int sb = bid >> 4;                    // score/finalize: batch
    int schunk = bid & 15;                // score/finalize: chunk

    // row-owned registers: thread owns row n = schunk*256 + tid of batch sb
    float cov_reg = 0.0f;
    float p_reg = 0.0f;
    float m_reg = __ldg(&mask[sb*N_ + schunk*256 + tid]);
    float closs_acc = 0.0f;

    size_t OUT_ATT = (size_t)B_ * T * DK_;

    for (int t = 0; t < T; t++) {
        int hb = t & 1;                   // hbuf/s/dec/partials parity

        // ======== Phase A: LSTM gates + c/h update (blocks 0..127) ========
        if (bid < 128) {
            // need: s from D(t-1) (32 seg0 blocks), h from all A(t-1),
            //       xn readers (B(t-1)) done before overwriting xn
            spin_ge(&g_cntS, 32u*t);
            spin_ge(&g_cntA, 128u*t);
            spin_ge(&g_cntB, 128u*t);
            acquire_fence();

            int j = bid;                  // hidden unit
            int half = lane >> 4;
            int koff2 = (lane & 15) * 2;
            const float4* Wih4 = (const float4*)Wih;
            const float4* Whh4 = (const float4*)Whh;
            #pragma unroll 4
            for (int i = 0; i < 16; i++) {
                int o = warp*16 + i;
                int gate = o >> 5, bb = o & 31;
                int r = gate*H_ + j;
                const float4* Wp4 = half ? Whh4 : Wih4;
                const float4* xp4 = half ? (const float4*)&g_hbuf[hb][bb*H_]
                                         : (const float4*)&g_s2[hb][bb*DK_];
                float4 w0 = __ldg(&Wp4[r*32 + koff2]);
                float4 w1 = __ldg(&Wp4[r*32 + koff2 + 1]);
                float4 x0 = xp4[koff2];
                float4 x1 = xp4[koff2 + 1];
                float acc = w0.x*x0.x + w0.y*x0.y + w0.z*x0.z + w0.w*x0.w
                          + w1.x*x1.x + w1.y*x1.y + w1.z*x1.z + w1.w*x1.w;
                #pragma unroll
                for (int off = 16; off > 0; off >>= 1)
                    acc += __shfl_xor_sync(0xffffffffu, acc, off);
                if (lane == 0) shm[o] = acc + __ldg(&bih[r]) + __ldg(&bhh[r]);
            }
            __syncthreads();
            if (tid < 32) {
                int bb = tid;
                float ig = sigmoid_f(shm[bb]);
                float fg = sigmoid_f(shm[32 + bb]);
                float gg = tanhf(shm[64 + bb]);
                float og = sigmoid_f(shm[96 + bb]);
                float cold = g_c[bb*H_ + j];
                float cn = fg * cold + ig * gg;
                float hn = og * tanhf(cn);
                g_c[bb*H_ + j] = cn;
                g_hbuf[hb ^ 1][bb*H_ + j] = hn;
                g_xn[bb*2*H_ + j] = hn;
                g_xn[bb*2*H_ + H_ + j] = cn;
            }
            block_signal(&g_cntA);

            // ======== Phase B: dec_fea = xn @ W_x ========
            spin_ge(&g_cntA, 128u*(t+1));                    // all xn written
            if (t >= 2) spin_ge(&g_cntC, 512u*(t-1));        // dec buffer free
            acquire_fence();

            int a = bid;
            const float4* WxT4 = (const float4*)g_WxT;
            float4 w0 = WxT4[a*64 + lane*2];
            float4 w1 = WxT4[a*64 + lane*2 + 1];
            #pragma unroll
            for (int i = 0; i < 4; i++) {
                int bb = warp*4 + i;
                const float4* xn4 = (const float4*)&g_xn[bb*2*H_];
                float4 x0 = xn4[lane*2];
                float4 x1 = xn4[lane*2 + 1];
                float acc = w0.x*x0.x + w0.y*x0.y + w0.z*x0.z + w0.w*x0.w
                          + w1.x*x1.x + w1.y*x1.y + w1.z*x1.z + w1.w*x1.w;
                #pragma unroll
                for (int off = 16; off > 0; off >>= 1)
                    acc += __shfl_xor_sync(0xffffffffu, acc, off);
                if (lane == 0) g_dec2[hb][bb*A_ + a] = acc;
            }
            block_signal(&g_cntB);
        }

        // ======== Phase C: attention scores + partial context (all) ========
        {
            spin_ge(&g_cntB, 128u*(t+1));   // dec ready
            acquire_fence();

            int b = sb, chunk = schunk;
            float4 dec4 = *(const float4*)&g_dec2[hb][b*A_ + lane*4];
            float4 wc4  = __ldg(&((const float4*)wc)[lane]);
            float4 v4   = __ldg(&((const float4*)v)[lane]);

            float4 ct = make_float4(0.f, 0.f, 0.f, 0.f);
            float Sacc = 0.0f;
            int n0 = chunk * TILE_ + warp * 32;
            const uint4* zi4 = (const uint4*)g_zi;

            #pragma unroll 4
            for (int r = 0; r < 32; r++) {
                size_t idx = (size_t)b*N_ + n0 + r;
                float cov = __shfl_sync(0xffffffffu, cov_reg, r);
                float m   = __shfl_sync(0xffffffffu, m_reg, r);
                uint4 raw = zi4[idx*32 + lane];       // one LDG.128: {zf x4, z x4}
                float2 fa = u_to_f2(raw.x);
                float2 fb = u_to_f2(raw.y);
                float t0 = tanh_fast(fmaf(cov, wc4.x, fa.x) + dec4.x);
                float t1 = tanh_fast(fmaf(cov, wc4.y, fa.y) + dec4.y);
                float t2 = tanh_fast(fmaf(cov, wc4.z, fb.x) + dec4.z);
                float t3 = tanh_fast(fmaf(cov, wc4.w, fb.y) + dec4.w);
                float e = v4.x*t0 + v4.y*t1 + v4.z*t2 + v4.w*t3;
                #pragma unroll
                for (int off = 16; off > 0; off >>= 1)
                    e += __shfl_xor_sync(0xffffffffu, e, off);
                // e bounded by ||v||_1 (~9): exp cannot overflow, skip global max
                float p = (m > 0.0f) ? __expf(e) : 0.0f;
                float2 za = u_to_f2(raw.z);
                float2 zb = u_to_f2(raw.w);
                ct.x = fmaf(p, za.x, ct.x);
                ct.y = fmaf(p, za.y, ct.y);
                ct.z = fmaf(p, zb.x, ct.z);
                ct.w = fmaf(p, zb.y, ct.w);
                if (lane == r) p_reg = p;
                Sacc += p;
            }

            if (tid < DK_) shm[tid] = 0.0f;
            if (lane == 0) shm[128 + warp] = Sacc;
            __syncthreads();
            atomicAdd(&shm[lane*4 + 0], ct.x);
            atomicAdd(&shm[lane*4 + 1], ct.y);
            atomicAdd(&shm[lane*4 + 2], ct.z);
            atomicAdd(&shm[lane*4 + 3], ct.w);
            __syncthreads();
            if (tid < DK_)
                g_CTp2[hb][(b*CH_ + chunk)*DK_ + tid] = shm[tid];
            if (tid == 0) {
                float S = 0.0f;
                #pragma unroll
                for (int w = 0; w < 8; w++) S += shm[128 + w];
                g_Sp2[hb][b*CH_ + chunk] = S;
            }
            // release partials + dec-read-done
            __threadfence();
            __syncthreads();
            if (tid == 0) {
                atomicAdd(&g_cntSp[b], 1u);
                atomicAdd(&g_cntC, 1u);
            }
        }

        // ======== Phase D: finalize (all blocks) ========
        {
            spin_ge(&g_cntSp[sb], 16u*(t+1));   // all 16 chunks of this batch
            acquire_fence();

            int b = sb, seg = schunk;
            if (tid < CH_) shm[tid] = g_Sp2[hb][b*CH_ + tid];
            __syncthreads();
            float S = 0.0f;
            #pragma unroll
            for (int ch = 0; ch < CH_; ch++) S += shm[ch];
            float invS = 1.0f / S;

            if (seg == 0 && tid < DK_) {
                float ctv = 0.0f;
                #pragma unroll
                for (int ch = 0; ch < CH_; ch++)
                    ctv += g_CTp2[hb][(b*CH_ + ch)*DK_ + tid];
                ctv *= invS;
                out[(size_t)(b*T + t)*DK_ + tid] = ctv;
                g_s2[hb ^ 1][b*DK_ + tid] = ctv;  // next LSTM input
            }

            int n = seg*256 + tid;
            float attn = p_reg * invS;
            float cl = fminf(attn, cov_reg);      // coverage BEFORE update
            cov_reg += attn;
            out[OUT_ATT + (size_t)(b*T + t)*N_ + n] = attn;

            #pragma unroll
            for (int off = 16; off > 0; off >>= 1)
                cl += __shfl_xor_sync(0xffffffffu, cl, off);
            __syncthreads();
            if (lane == 0) shm[16 + warp] = cl;
            __syncthreads();
            if (tid == 0) {
                float s = 0.0f;
                #pragma unroll
                for (int w = 0; w < 8; w++) s += shm[16 + w];
                closs_acc += s;
            }
            if (seg == 0) {                       // release s for A(t+1)
                __threadfence();
                __syncthreads();
                if (tid == 0) atomicAdd(&g_cntS, 1u);
            }
        }
    }

    // deterministic closs: ordered reduction of per-block partials
    if (tid == 0) g_clp[bid] = closs_acc;
    block_signal(&g_cntDone);
    if (bid == 0 && tid == 0) {
        volatile unsigned* d = &g_cntDone;
        while (*d < GRID_) __nanosleep(128);
        __threadfence();
        float s = 0.0f;
        for (int i = 0; i < GRID_; i++) s += g_clp[i];
        out[out_size - 1] = s / (float)B_;
    }
}

// ---------------- host driver ----------------------------------------------
extern "C" void kernel_launch(void* const* d_in, const int* in_sizes, int n_in,
                              void* d_out, int out_size) {
    const float* z     = (const float*)d_in[0];
    const float* mask  = (const float*)d_in[1];
    const float* h0    = (const float*)d_in[2];
    const float* c0    = (const float*)d_in[3];
    const float* W_ih  = (const float*)d_in[4];
    const float* W_hh  = (const float*)d_in[5];
    const float* b_ih  = (const float*)d_in[6];
    const float* b_hh  = (const float*)d_in[7];
    const float* W_x   = (const float*)d_in[8];
    const float* W_z   = (const float*)d_in[9];
    const float* w_c   = (const float*)d_in[10];
    const float* b_attn= (const float*)d_in[11];
    const float* v     = (const float*)d_in[12];
    float* out = (float*)d_out;

    int T = (out_size - 1) / (B_ * (DK_ + N_));

    zfea_kernel<<<(B_*N_)/64, 256>>>(z, W_z, b_attn, W_x, h0, c0);
    persistent_kernel<<<GRID_, 256>>>(out, T, out_size,
                                      W_ih, W_hh, b_ih, b_hh,
                                      mask, w_c, v);
}

// round 9
// speedup vs baseline: 1.5186x; 1.5186x over previous
#include <cuda_runtime.h>
#include <cuda_fp16.h>
#include <cuda_bf16.h>

// Problem constants
#define B_   32
#define N_   4096
#define DK_  128
#define H_   128
#define A_   128
#define CH_  16
#define TILE_ 256
#define NB_  544            // 512 CD blocks + 32 AB blocks

// ---------------- scratch (device globals) ---------------------------------
// Interleaved fp16: per row idx, lane l owns halves [l*8..l*8+7] =
// {zfea[4l..4l+3], z[4l..4l+3]} -> one uint4 (16B) load per (row, lane).
__device__ __half g_zi[(size_t)B_*N_*256];   // 67MB
__device__ float g_Wg[512*256];        // packed gate weights: row j = [Wih[j] | Whh[j]]
__device__ float g_bg[512];            // bih + bhh
__device__ float g_WxT[A_*256];        // transposed W_x: [a][k]
__device__ float g_s[B_*DK_];          // context (LSTM input), single buffer
__device__ float g_dec[B_*A_];         // dec_fea, single buffer
__device__ float g_Sp2[2][B_*CH_];     // parity-buffered softmax partials
__device__ float g_CTp2[2][B_*CH_*DK_]; // parity-buffered context partials
__device__ float g_clp[NB_];           // per-block closs partials (deterministic)
// per-batch counters, each on its own 128B line
__device__ unsigned g_readyAB[B_*32];  // AB steps completed for batch b
__device__ unsigned g_SpCnt[B_*32];    // C partials count (16/step, monotonic)
__device__ unsigned g_readyS[B_*32];   // D(seg0) steps completed (s written)
__device__ unsigned g_done;

__device__ __forceinline__ float tanh_fast(float x) {
    float y; asm("tanh.approx.f32 %0, %1;" : "=f"(y) : "f"(x)); return y;
}
__device__ __forceinline__ float sigmoid_f(float x) {
    return 1.0f / (1.0f + __expf(-x));
}
__device__ __forceinline__ unsigned h2_to_u(__half2 h) {
    return *reinterpret_cast<unsigned*>(&h);
}
__device__ __forceinline__ float2 u_to_f2(unsigned u) {
    __half2 h = *reinterpret_cast<__half2*>(&u);
    return __half22float2(h);
}

// block-wide wait: tid0 spins until *c >= tgt, then acquire + syncthreads
__device__ __forceinline__ void waitc(volatile unsigned* c, unsigned tgt) {
    if (threadIdx.x == 0) {
        int sp = 0;
        while (*c < tgt) { if (++sp > 96) { __nanosleep(32); } }
        __threadfence();
    }
    __syncthreads();
}
// block-wide signal: release writes, tid0 bumps counter
__device__ __forceinline__ void signalc(unsigned* c) {
    __threadfence();
    __syncthreads();
    if (threadIdx.x == 0) atomicAdd(c, 1u);
}

// ---------------- one-time: zfea GEMM + weight packing + counter reset -----
// grid 2048 x 256
__global__ void zfea_kernel(const float* __restrict__ z, const float* __restrict__ Wz,
                            const float* __restrict__ battn,
                            const float* __restrict__ Wih, const float* __restrict__ Whh,
                            const float* __restrict__ bih, const float* __restrict__ bhh,
                            const float* __restrict__ Wx) {
    int t = threadIdx.x;
    int bid = blockIdx.x;

    if (bid == 0) {
        if (t < B_) { g_readyAB[t*32] = 0; g_SpCnt[t*32] = 0; g_readyS[t*32] = 0; }
        if (t == 0) g_done = 0;
    }
    if (bid < 512) {                      // pack gate weights: row j = bid
        int j = bid;
        g_Wg[j*256 + t] = (t < 128) ? Wih[j*128 + t] : Whh[j*128 + (t-128)];
        if (t == 0) g_bg[j] = bih[j] + bhh[j];
    } else if (bid < 640) {               // W_x transpose: 32768 elems
        int i = (bid - 512)*256 + t;
        int a = i >> 8, k = i & 255;
        g_WxT[i] = Wx[k*A_ + a];
    }

    __shared__ float zs[64*DK_];
    int rowBase = bid * 64;
    const float* zsrc = z + (size_t)rowBase * DK_;
    #pragma unroll
    for (int k = 0; k < 32; k++) zs[t + k*256] = zsrc[t + k*256];
    __syncthreads();

    int tx = t & 31, ty = t >> 5;
    float acc[8][4];
    #pragma unroll
    for (int i = 0; i < 8; i++)
        #pragma unroll
        for (int c = 0; c < 4; c++) acc[i][c] = 0.0f;

    const float4* Wz4 = (const float4*)Wz;
    #pragma unroll 4
    for (int d = 0; d < DK_; d++) {
        float4 w = __ldg(&Wz4[d*32 + tx]);
        #pragma unroll
        for (int i = 0; i < 8; i++) {
            float zv = zs[(ty + 8*i)*DK_ + d];
            acc[i][0] = fmaf(zv, w.x, acc[i][0]);
            acc[i][1] = fmaf(zv, w.y, acc[i][1]);
            acc[i][2] = fmaf(zv, w.z, acc[i][2]);
            acc[i][3] = fmaf(zv, w.w, acc[i][3]);
        }
    }
    float4 bb = __ldg(&((const float4*)battn)[tx]);
    uint4* outp = (uint4*)g_zi;
    #pragma unroll
    for (int i = 0; i < 8; i++) {
        size_t r = rowBase + ty + 8*i;
        int lr = ty + 8*i;
        __half2 f0 = __floats2half2_rn(acc[i][0] + bb.x, acc[i][1] + bb.y);
        __half2 f1 = __floats2half2_rn(acc[i][2] + bb.z, acc[i][3] + bb.w);
        __half2 z0 = __floats2half2_rn(zs[lr*DK_ + tx*4],     zs[lr*DK_ + tx*4 + 1]);
        __half2 z1 = __floats2half2_rn(zs[lr*DK_ + tx*4 + 2], zs[lr*DK_ + tx*4 + 3]);
        uint4 pk;
        pk.x = h2_to_u(f0); pk.y = h2_to_u(f1);
        pk.z = h2_to_u(z0); pk.w = h2_to_u(z1);
        outp[r*32 + tx] = pk;
    }
}

// ---------------- persistent: 32 independent per-batch pipelines ------------
// bid 0..511: CD blocks (batch = bid>>4, chunk/seg = bid&15)
// bid 512..543: AB blocks (batch = bid-512), LSTM h/c resident in smem
__global__ __launch_bounds__(256, 4) void persistent_kernel(
        float* __restrict__ out, int T, int out_size,
        const float* __restrict__ mask,
        const float* __restrict__ wc, const float* __restrict__ v,
        const float* __restrict__ h0, const float* __restrict__ c0) {
    int bid = blockIdx.x;
    int tid = threadIdx.x;
    int warp = tid >> 5, lane = tid & 31;
    float closs_acc = 0.0f;
    size_t OUT_ATT = (size_t)B_ * T * DK_;

    if (bid >= 512) {
        // ==================== AB pipeline (one block per batch) ====================
        int b = bid - 512;
        __shared__ float xs[256];     // [s | h]
        __shared__ float hc[256];     // persistent h[0..127], c[128..255]
        __shared__ float gates[512];
        __shared__ float xh[256];     // [h_new | c_new]

        if (tid < 128) hc[tid] = h0[b*H_ + tid];
        else           hc[tid] = c0[b*H_ + (tid - 128)];
        __syncthreads();

        const float4* Wg4  = (const float4*)g_Wg;
        const float4* WxT4 = (const float4*)g_WxT;

        for (int t = 0; t < T; t++) {
            if (t > 0) waitc(&g_readyS[b*32], (unsigned)t);
            if (tid < 128) xs[tid] = (t == 0) ? 0.0f : g_s[b*DK_ + tid];
            else           xs[tid] = hc[tid - 128];
            __syncthreads();

            float4 xa = ((const float4*)xs)[lane*2];
            float4 xb = ((const float4*)xs)[lane*2 + 1];
            // gates: warp w -> j = w*64 .. w*64+63
            #pragma unroll 8
            for (int i = 0; i < 64; i++) {
                int j = warp*64 + i;
                float4 w0 = __ldg(&Wg4[j*64 + lane*2]);
                float4 w1 = __ldg(&Wg4[j*64 + lane*2 + 1]);
                float acc = w0.x*xa.x + w0.y*xa.y + w0.z*xa.z + w0.w*xa.w
                          + w1.x*xb.x + w1.y*xb.y + w1.z*xb.z + w1.w*xb.w;
                #pragma unroll
                for (int off = 16; off > 0; off >>= 1)
                    acc += __shfl_xor_sync(0xffffffffu, acc, off);
                if (lane == 0) gates[j] = acc + g_bg[j];
            }
            __syncthreads();
            if (tid < 128) {
                int j = tid;
                float cn = sigmoid_f(gates[H_ + j]) * hc[128 + j]
                         + sigmoid_f(gates[j]) * tanhf(gates[2*H_ + j]);
                float hn = sigmoid_f(gates[3*H_ + j]) * tanhf(cn);
                hc[j] = hn; hc[128 + j] = cn;
                xh[j] = hn; xh[128 + j] = cn;
            }
            __syncthreads();
            // dec: warp w -> a = w*16 .. w*16+15
            float4 ya = ((const float4*)xh)[lane*2];
            float4 yb = ((const float4*)xh)[lane*2 + 1];
            #pragma unroll 4
            for (int i = 0; i < 16; i++) {
                int a = warp*16 + i;
                float4 w0 = __ldg(&WxT4[a*64 + lane*2]);
                float4 w1 = __ldg(&WxT4[a*64 + lane*2 + 1]);
                float acc = w0.x*ya.x + w0.y*ya.y + w0.z*ya.z + w0.w*ya.w
                          + w1.x*yb.x + w1.y*yb.y + w1.z*yb.z + w1.w*yb.w;
                #pragma unroll
                for (int off = 16; off > 0; off >>= 1)
                    acc += __shfl_xor_sync(0xffffffffu, acc, off);
                if (lane == 0) g_dec[b*A_ + a] = acc;
            }
            signalc(&g_readyAB[b*32]);
        }
    } else {
        // ==================== CD pipeline (16 blocks per batch) ====================
        int b = bid >> 4, seg = bid & 15;
        __shared__ float shm[136];

        float cov_reg = 0.0f;
        float p_reg = 0.0f;
        float m_reg = __ldg(&mask[b*N_ + seg*256 + tid]);

        for (int t = 0; t < T; t++) {
            int hb = t & 1;

            // ---- Phase C: scores + partial context ----
            waitc(&g_readyAB[b*32], (unsigned)(t + 1));

            float4 dec4 = *(const float4*)&g_dec[b*A_ + lane*4];
            float4 wc4  = __ldg(&((const float4*)wc)[lane]);
            float4 v4   = __ldg(&((const float4*)v)[lane]);

            float4 ct = make_float4(0.f, 0.f, 0.f, 0.f);
            float Sacc = 0.0f;
            int n0 = seg * TILE_ + warp * 32;
            const uint4* zi4 = (const uint4*)g_zi;

            #pragma unroll 4
            for (int r = 0; r < 32; r++) {
                size_t idx = (size_t)b*N_ + n0 + r;
                float cov = __shfl_sync(0xffffffffu, cov_reg, r);
                float m   = __shfl_sync(0xffffffffu, m_reg, r);
                uint4 raw = zi4[idx*32 + lane];       // one LDG.128: {zf x4, z x4}
                float2 fa = u_to_f2(raw.x);
                float2 fb = u_to_f2(raw.y);
                float t0 = tanh_fast(fmaf(cov, wc4.x, fa.x) + dec4.x);
                float t1 = tanh_fast(fmaf(cov, wc4.y, fa.y) + dec4.y);
                float t2 = tanh_fast(fmaf(cov, wc4.z, fb.x) + dec4.z);
                float t3 = tanh_fast(fmaf(cov, wc4.w, fb.y) + dec4.w);
                float e = v4.x*t0 + v4.y*t1 + v4.z*t2 + v4.w*t3;
                #pragma unroll
                for (int off = 16; off > 0; off >>= 1)
                    e += __shfl_xor_sync(0xffffffffu, e, off);
                // e bounded by ||v||_1 (~9): exp cannot overflow, skip global max
                float p = (m > 0.0f) ? __expf(e) : 0.0f;
                float2 za = u_to_f2(raw.z);
                float2 zb = u_to_f2(raw.w);
                ct.x = fmaf(p, za.x, ct.x);
                ct.y = fmaf(p, za.y, ct.y);
                ct.z = fmaf(p, zb.x, ct.z);
                ct.w = fmaf(p, zb.y, ct.w);
                if (lane == r) p_reg = p;
                Sacc += p;
            }

            if (tid < DK_) shm[tid] = 0.0f;
            if (lane == 0) shm[128 + warp] = Sacc;
            __syncthreads();
            atomicAdd(&shm[lane*4 + 0], ct.x);
            atomicAdd(&shm[lane*4 + 1], ct.y);
            atomicAdd(&shm[lane*4 + 2], ct.z);
            atomicAdd(&shm[lane*4 + 3], ct.w);
            __syncthreads();
            if (tid < DK_)
                g_CTp2[hb][(b*CH_ + seg)*DK_ + tid] = shm[tid];
            if (tid == 0) {
                float S = 0.0f;
                #pragma unroll
                for (int w = 0; w < 8; w++) S += shm[128 + w];
                g_Sp2[hb][b*CH_ + seg] = S;
            }
            signalc(&g_SpCnt[b*32]);

            // ---- Phase D: finalize ----
            waitc(&g_SpCnt[b*32], (unsigned)(16*(t + 1)));

            if (tid < CH_) shm[tid] = g_Sp2[hb][b*CH_ + tid];
            __syncthreads();
            float S = 0.0f;
            #pragma unroll
            for (int ch = 0; ch < CH_; ch++) S += shm[ch];
            float invS = 1.0f / S;

            if (seg == 0 && tid < DK_) {
                float ctv = 0.0f;
                #pragma unroll
                for (int ch = 0; ch < CH_; ch++)
                    ctv += g_CTp2[hb][(b*CH_ + ch)*DK_ + tid];
                ctv *= invS;
                out[(size_t)(b*T + t)*DK_ + tid] = ctv;
                g_s[b*DK_ + tid] = ctv;           // next LSTM input
            }

            int n = seg*256 + tid;
            float attn = p_reg * invS;
            float cl = fminf(attn, cov_reg);      // coverage BEFORE update
            cov_reg += attn;
            out[OUT_ATT + (size_t)(b*T + t)*N_ + n] = attn;

            #pragma unroll
            for (int off = 16; off > 0; off >>= 1)
                cl += __shfl_xor_sync(0xffffffffu, cl, off);
            __syncthreads();
            if (lane == 0) shm[16 + warp] = cl;
            __syncthreads();
            if (tid == 0) {
                float s = 0.0f;
                #pragma unroll
                for (int w = 0; w < 8; w++) s += shm[16 + w];
                closs_acc += s;
            }

            if (seg == 0) signalc(&g_readyS[b*32]);
            else { __syncthreads(); }
        }
    }

    // deterministic closs: ordered reduction of per-block partials
    if (tid == 0) g_clp[bid] = closs_acc;
    __threadfence();
    __syncthreads();
    if (tid == 0) atomicAdd(&g_done, 1u);
    if (bid == 0 && tid == 0) {
        volatile unsigned* d = &g_done;
        while (*d < NB_) __nanosleep(128);
        __threadfence();
        float s = 0.0f;
        for (int i = 0; i < NB_; i++) s += g_clp[i];
        out[out_size - 1] = s / (float)B_;
    }
}

// ---------------- host driver ----------------------------------------------
extern "C" void kernel_launch(void* const* d_in, const int* in_sizes, int n_in,
                              void* d_out, int out_size) {
    const float* z     = (const float*)d_in[0];
    const float* mask  = (const float*)d_in[1];
    const float* h0    = (const float*)d_in[2];
    const float* c0    = (const float*)d_in[3];
    const float* W_ih  = (const float*)d_in[4];
    const float* W_hh  = (const float*)d_in[5];
    const float* b_ih  = (const float*)d_in[6];
    const float* b_hh  = (const float*)d_in[7];
    const float* W_x   = (const float*)d_in[8];
    const float* W_z   = (const float*)d_in[9];
    const float* w_c   = (const float*)d_in[10];
    const float* b_attn= (const float*)d_in[11];
    const float* v     = (const float*)d_in[12];
    float* out = (float*)d_out;

    int T = (out_size - 1) / (B_ * (DK_ + N_));

    zfea_kernel<<<(B_*N_)/64, 256>>>(z, W_z, b_attn, W_ih, W_hh, b_ih, b_hh, W_x);
    persistent_kernel<<<NB_, 256>>>(out, T, out_size, mask, w_c, v, h0, c0);
}

// round 10
// speedup vs baseline: 1.6745x; 1.1026x over previous
#include <cuda_runtime.h>
#include <cuda_fp16.h>
#include <cuda_bf16.h>

// Problem constants
#define B_   32
#define N_   4096
#define DK_  128
#define H_   128
#define A_   128
#define CH_  16
#define TILE_ 256
#define NB_  544            // 512 CD blocks + 32 AB blocks

// ---------------- scratch (device globals) ---------------------------------
// Interleaved fp16: per row idx, lane l owns halves [l*8..l*8+7] =
// {zfea[4l..4l+3], z[4l..4l+3]} -> one uint4 (16B) load per (row, lane).
__device__ __half g_zi[(size_t)B_*N_*256];   // 67MB
__device__ float g_Wg[512*256];        // packed gate weights: row j = [Wih[j] | Whh[j]]
__device__ float g_bg[512];            // bih + bhh
__device__ float g_WxT[A_*256];        // transposed W_x: [a][k]
__device__ float g_dec[B_*A_];         // dec_fea, single buffer
__device__ float g_Sp2[2][B_*CH_];     // parity-buffered softmax partials
__device__ float g_CTp2[2][B_*CH_*DK_]; // parity-buffered context partials
__device__ float g_clp[NB_];           // per-block closs partials (deterministic)
// per-batch counters, each on its own 128B line
__device__ unsigned g_readyAB[B_*32];  // AB steps completed for batch b
__device__ unsigned g_SpCnt[B_*32];    // C partials count (16/step, monotonic)
__device__ unsigned g_done;

__device__ __forceinline__ float tanh_fast(float x) {
    float y; asm("tanh.approx.f32 %0, %1;" : "=f"(y) : "f"(x)); return y;
}
__device__ __forceinline__ float sigmoid_f(float x) {
    return 1.0f / (1.0f + __expf(-x));
}
__device__ __forceinline__ unsigned h2_to_u(__half2 h) {
    return *reinterpret_cast<unsigned*>(&h);
}
__device__ __forceinline__ float2 u_to_f2(unsigned u) {
    __half2 h = *reinterpret_cast<__half2*>(&u);
    return __half22float2(h);
}

// block-wide wait: tid0 spins until *c >= tgt, then acquire + syncthreads
__device__ __forceinline__ void waitc(volatile unsigned* c, unsigned tgt) {
    if (threadIdx.x == 0) {
        int sp = 0;
        while (*c < tgt) { if (++sp > 2048) __nanosleep(64); }
        __threadfence();
    }
    __syncthreads();
}
// block-wide signal: release writes, tid0 bumps counter
__device__ __forceinline__ void signalc(unsigned* c) {
    __threadfence();
    __syncthreads();
    if (threadIdx.x == 0) atomicAdd(c, 1u);
}

// ---------------- one-time: zfea GEMM + weight packing + counter reset -----
// grid 2048 x 256
__global__ void zfea_kernel(const float* __restrict__ z, const float* __restrict__ Wz,
                            const float* __restrict__ battn,
                            const float* __restrict__ Wih, const float* __restrict__ Whh,
                            const float* __restrict__ bih, const float* __restrict__ bhh,
                            const float* __restrict__ Wx) {
    int t = threadIdx.x;
    int bid = blockIdx.x;

    if (bid == 0) {
        if (t < B_) { g_readyAB[t*32] = 0; g_SpCnt[t*32] = 0; }
        if (t == 0) g_done = 0;
    }
    if (bid < 512) {                      // pack gate weights: row j = bid
        int j = bid;
        g_Wg[j*256 + t] = (t < 128) ? Wih[j*128 + t] : Whh[j*128 + (t-128)];
        if (t == 0) g_bg[j] = bih[j] + bhh[j];
    } else if (bid < 640) {               // W_x transpose: 32768 elems
        int i = (bid - 512)*256 + t;
        int a = i >> 8, k = i & 255;
        g_WxT[i] = Wx[k*A_ + a];
    }

    __shared__ float zs[64*DK_];
    int rowBase = bid * 64;
    const float* zsrc = z + (size_t)rowBase * DK_;
    #pragma unroll
    for (int k = 0; k < 32; k++) zs[t + k*256] = zsrc[t + k*256];
    __syncthreads();

    int tx = t & 31, ty = t >> 5;
    float acc[8][4];
    #pragma unroll
    for (int i = 0; i < 8; i++)
        #pragma unroll
        for (int c = 0; c < 4; c++) acc[i][c] = 0.0f;

    const float4* Wz4 = (const float4*)Wz;
    #pragma unroll 4
    for (int d = 0; d < DK_; d++) {
        float4 w = __ldg(&Wz4[d*32 + tx]);
        #pragma unroll
        for (int i = 0; i < 8; i++) {
            float zv = zs[(ty + 8*i)*DK_ + d];
            acc[i][0] = fmaf(zv, w.x, acc[i][0]);
            acc[i][1] = fmaf(zv, w.y, acc[i][1]);
            acc[i][2] = fmaf(zv, w.z, acc[i][2]);
            acc[i][3] = fmaf(zv, w.w, acc[i][3]);
        }
    }
    float4 bb = __ldg(&((const float4*)battn)[tx]);
    uint4* outp = (uint4*)g_zi;
    #pragma unroll
    for (int i = 0; i < 8; i++) {
        size_t r = rowBase + ty + 8*i;
        int lr = ty + 8*i;
        __half2 f0 = __floats2half2_rn(acc[i][0] + bb.x, acc[i][1] + bb.y);
        __half2 f1 = __floats2half2_rn(acc[i][2] + bb.z, acc[i][3] + bb.w);
        __half2 z0 = __floats2half2_rn(zs[lr*DK_ + tx*4],     zs[lr*DK_ + tx*4 + 1]);
        __half2 z1 = __floats2half2_rn(zs[lr*DK_ + tx*4 + 2], zs[lr*DK_ + tx*4 + 3]);
        uint4 pk;
        pk.x = h2_to_u(f0); pk.y = h2_to_u(f1);
        pk.z = h2_to_u(z0); pk.w = h2_to_u(z1);
        outp[r*32 + tx] = pk;
    }
}

// ---------------- persistent: 32 independent per-batch pipelines ------------
// bid 0..511: CD blocks (batch = bid>>4, seg = bid&15)
// bid 512..543: AB blocks (batch = bid-512): context assembly + LSTM + dec
__global__ __launch_bounds__(256, 4) void persistent_kernel(
        float* __restrict__ out, int T, int out_size,
        const float* __restrict__ mask,
        const float* __restrict__ wc, const float* __restrict__ v,
        const float* __restrict__ h0, const float* __restrict__ c0) {
    int bid = blockIdx.x;
    int tid = threadIdx.x;
    int warp = tid >> 5, lane = tid & 31;
    float closs_acc = 0.0f;
    size_t OUT_ATT = (size_t)B_ * T * DK_;

    if (bid >= 512) {
        // ==================== AB pipeline (one block per batch) ====================
        // Per step: assemble s(t-1) from partials, LSTM, dec_fea, signal.
        int b = bid - 512;
        __shared__ float xs[256];     // [s | h]
        __shared__ float hc[256];     // persistent h[0..127], c[128..255]
        __shared__ float gates[512];
        __shared__ float xh[256];     // [h_new | c_new]
        __shared__ float sp_s[CH_];

        if (tid < 128) hc[tid] = h0[b*H_ + tid];
        else           hc[tid] = c0[b*H_ + (tid - 128)];
        __syncthreads();

        const float4* Wg4  = (const float4*)g_Wg;
        const float4* WxT4 = (const float4*)g_WxT;

        for (int t = 0; t < T; t++) {
            // ---- context assembly: s(t-1) = sum_ch CTp / S ----
            if (t > 0) {
                int hb1 = (t - 1) & 1;
                waitc(&g_SpCnt[b*32], (unsigned)(16*t));
                if (tid < CH_) sp_s[tid] = g_Sp2[hb1][b*CH_ + tid];
                __syncthreads();
                if (tid < 128) {
                    float S = 0.0f;
                    #pragma unroll
                    for (int ch = 0; ch < CH_; ch++) S += sp_s[ch];
                    float invS = 1.0f / S;
                    float ctv = 0.0f;
                    #pragma unroll
                    for (int ch = 0; ch < CH_; ch++)
                        ctv += g_CTp2[hb1][(b*CH_ + ch)*DK_ + tid];
                    ctv *= invS;
                    xs[tid] = ctv;
                    out[(size_t)(b*T + (t-1))*DK_ + tid] = ctv;  // text output
                }
            } else {
                if (tid < 128) xs[tid] = 0.0f;
            }
            if (tid >= 128) xs[tid] = hc[tid - 128];
            __syncthreads();

            float4 xa = ((const float4*)xs)[lane*2];
            float4 xb = ((const float4*)xs)[lane*2 + 1];
            // gates: warp w -> j = w*64 .. w*64+63
            #pragma unroll 8
            for (int i = 0; i < 64; i++) {
                int j = warp*64 + i;
                float4 w0 = __ldg(&Wg4[j*64 + lane*2]);
                float4 w1 = __ldg(&Wg4[j*64 + lane*2 + 1]);
                float acc = w0.x*xa.x + w0.y*xa.y + w0.z*xa.z + w0.w*xa.w
                          + w1.x*xb.x + w1.y*xb.y + w1.z*xb.z + w1.w*xb.w;
                #pragma unroll
                for (int off = 16; off > 0; off >>= 1)
                    acc += __shfl_xor_sync(0xffffffffu, acc, off);
                if (lane == 0) gates[j] = acc + g_bg[j];
            }
            __syncthreads();
            if (tid < 128) {
                int j = tid;
                float cn = sigmoid_f(gates[H_ + j]) * hc[128 + j]
                         + sigmoid_f(gates[j]) * tanhf(gates[2*H_ + j]);
                float hn = sigmoid_f(gates[3*H_ + j]) * tanhf(cn);
                hc[j] = hn; hc[128 + j] = cn;
                xh[j] = hn; xh[128 + j] = cn;
            }
            __syncthreads();
            // dec: warp w -> a = w*16 .. w*16+15
            float4 ya = ((const float4*)xh)[lane*2];
            float4 yb = ((const float4*)xh)[lane*2 + 1];
            #pragma unroll 4
            for (int i = 0; i < 16; i++) {
                int a = warp*16 + i;
                float4 w0 = __ldg(&WxT4[a*64 + lane*2]);
                float4 w1 = __ldg(&WxT4[a*64 + lane*2 + 1]);
                float acc = w0.x*ya.x + w0.y*ya.y + w0.z*ya.z + w0.w*ya.w
                          + w1.x*yb.x + w1.y*yb.y + w1.z*yb.z + w1.w*yb.w;
                #pragma unroll
                for (int off = 16; off > 0; off >>= 1)
                    acc += __shfl_xor_sync(0xffffffffu, acc, off);
                if (lane == 0) g_dec[b*A_ + a] = acc;
            }
            signalc(&g_readyAB[b*32]);
        }
        // final step's text output
        {
            int hb1 = (T - 1) & 1;
            waitc(&g_SpCnt[b*32], (unsigned)(16*T));
            if (tid < CH_) sp_s[tid] = g_Sp2[hb1][b*CH_ + tid];
            __syncthreads();
            if (tid < 128) {
                float S = 0.0f;
                #pragma unroll
                for (int ch = 0; ch < CH_; ch++) S += sp_s[ch];
                float invS = 1.0f / S;
                float ctv = 0.0f;
                #pragma unroll
                for (int ch = 0; ch < CH_; ch++)
                    ctv += g_CTp2[hb1][(b*CH_ + ch)*DK_ + tid];
                out[(size_t)(b*T + (T-1))*DK_ + tid] = ctv * invS;
            }
        }
    } else {
        // ==================== CD pipeline (16 blocks per batch) ====================
        int b = bid >> 4, seg = bid & 15;
        __shared__ float shm[136];

        float cov_reg = 0.0f;
        float p_reg = 0.0f;
        float m_reg = __ldg(&mask[b*N_ + seg*256 + tid]);
        float4 wc4  = __ldg(&((const float4*)wc)[lane]);
        float4 v4   = __ldg(&((const float4*)v)[lane]);
        const uint4* zi4 = (const uint4*)g_zi;
        int n0 = seg * TILE_ + warp * 32;

        for (int t = 0; t < T; t++) {
            int hb = t & 1;

            // ---- Phase C: scores + partial context ----
            waitc(&g_readyAB[b*32], (unsigned)(t + 1));

            float4 dec4 = *(const float4*)&g_dec[b*A_ + lane*4];
            float4 ct = make_float4(0.f, 0.f, 0.f, 0.f);
            float Sacc = 0.0f;

            #pragma unroll 4
            for (int r = 0; r < 32; r++) {
                size_t idx = (size_t)b*N_ + n0 + r;
                float cov = __shfl_sync(0xffffffffu, cov_reg, r);
                float m   = __shfl_sync(0xffffffffu, m_reg, r);
                uint4 raw = zi4[idx*32 + lane];       // one LDG.128: {zf x4, z x4}
                float2 fa = u_to_f2(raw.x);
                float2 fb = u_to_f2(raw.y);
                float t0 = tanh_fast(fmaf(cov, wc4.x, fa.x) + dec4.x);
                float t1 = tanh_fast(fmaf(cov, wc4.y, fa.y) + dec4.y);
                float t2 = tanh_fast(fmaf(cov, wc4.z, fb.x) + dec4.z);
                float t3 = tanh_fast(fmaf(cov, wc4.w, fb.y) + dec4.w);
                float e = v4.x*t0 + v4.y*t1 + v4.z*t2 + v4.w*t3;
                #pragma unroll
                for (int off = 16; off > 0; off >>= 1)
                    e += __shfl_xor_sync(0xffffffffu, e, off);
                // e bounded by ||v||_1 (~9): exp cannot overflow, skip global max
                float p = (m > 0.0f) ? __expf(e) : 0.0f;
                float2 za = u_to_f2(raw.z);
                float2 zb = u_to_f2(raw.w);
                ct.x = fmaf(p, za.x, ct.x);
                ct.y = fmaf(p, za.y, ct.y);
                ct.z = fmaf(p, zb.x, ct.z);
                ct.w = fmaf(p, zb.y, ct.w);
                if (lane == r) p_reg = p;
                Sacc += p;
            }

            if (tid < DK_) shm[tid] = 0.0f;
            if (lane == 0) shm[128 + warp] = Sacc;
            __syncthreads();
            atomicAdd(&shm[lane*4 + 0], ct.x);
            atomicAdd(&shm[lane*4 + 1], ct.y);
            atomicAdd(&shm[lane*4 + 2], ct.z);
            atomicAdd(&shm[lane*4 + 3], ct.w);
            __syncthreads();
            if (tid < DK_)
                g_CTp2[hb][(b*CH_ + seg)*DK_ + tid] = shm[tid];
            if (tid == 0) {
                float S = 0.0f;
                #pragma unroll
                for (int w = 0; w < 8; w++) S += shm[128 + w];
                g_Sp2[hb][b*CH_ + seg] = S;
            }
            signalc(&g_SpCnt[b*32]);

            // ---- D-lite (off critical path): attn out, coverage, closs ----
            waitc(&g_SpCnt[b*32], (unsigned)(16*(t + 1)));
            if (tid < CH_) shm[tid] = g_Sp2[hb][b*CH_ + tid];
            __syncthreads();
            float S = 0.0f;
            #pragma unroll
            for (int ch = 0; ch < CH_; ch++) S += shm[ch];
            float invS = 1.0f / S;

            int n = seg*256 + tid;
            float attn = p_reg * invS;
            float cl = fminf(attn, cov_reg);      // coverage BEFORE update
            cov_reg += attn;
            out[OUT_ATT + (size_t)(b*T + t)*N_ + n] = attn;

            #pragma unroll
            for (int off = 16; off > 0; off >>= 1)
                cl += __shfl_xor_sync(0xffffffffu, cl, off);
            __syncthreads();
            if (lane == 0) shm[16 + warp] = cl;
            __syncthreads();
            if (tid == 0) {
                float s = 0.0f;
                #pragma unroll
                for (int w = 0; w < 8; w++) s += shm[16 + w];
                closs_acc += s;
            }
            __syncthreads();
        }
    }

    // deterministic closs: ordered reduction of per-block partials
    if (tid == 0) g_clp[bid] = closs_acc;
    __threadfence();
    __syncthreads();
    if (tid == 0) atomicAdd(&g_done, 1u);
    if (bid == 0 && tid == 0) {
        volatile unsigned* d = &g_done;
        while (*d < NB_) __nanosleep(128);
        __threadfence();
        float s = 0.0f;
        for (int i = 0; i < NB_; i++) s += g_clp[i];
        out[out_size - 1] = s / (float)B_;
    }
}

// ---------------- host driver ----------------------------------------------
extern "C" void kernel_launch(void* const* d_in, const int* in_sizes, int n_in,
                              void* d_out, int out_size) {
    const float* z     = (const float*)d_in[0];
    const float* mask  = (const float*)d_in[1];
    const float* h0    = (const float*)d_in[2];
    const float* c0    = (const float*)d_in[3];
    const float* W_ih  = (const float*)d_in[4];
    const float* W_hh  = (const float*)d_in[5];
    const float* b_ih  = (const float*)d_in[6];
    const float* b_hh  = (const float*)d_in[7];
    const float* W_x   = (const float*)d_in[8];
    const float* W_z   = (const float*)d_in[9];
    const float* w_c   = (const float*)d_in[10];
    const float* b_attn= (const float*)d_in[11];
    const float* v     = (const float*)d_in[12];
    float* out = (float*)d_out;

    int T = (out_size - 1) / (B_ * (DK_ + N_));

    zfea_kernel<<<(B_*N_)/64, 256>>>(z, W_z, b_attn, W_ih, W_hh, b_ih, b_hh, W_x);
    persistent_kernel<<<NB_, 256>>>(out, T, out_size, mask, w_c, v, h0, c0);
}

// round 11
// speedup vs baseline: 1.8042x; 1.0774x over previous
#include <cuda_runtime.h>
#include <cuda_fp16.h>
#include <cuda_bf16.h>

// Problem constants
#define B_   32
#define N_   4096
#define DK_  128
#define H_   128
#define A_   128
#define CH_  16
#define TILE_ 256
#define NB_  288            // 256 CD blocks (16 per batch-pair) + 32 AB blocks

// ---------------- scratch (device globals) ---------------------------------
// Interleaved fp16: per row idx, lane l owns halves [l*8..l*8+7] =
// {zfea[4l..4l+3], z[4l..4l+3]} -> one uint4 (16B) load per (row, lane).
__device__ __half g_zi[(size_t)B_*N_*256];   // 67MB
__device__ float g_Wg[512*256];        // packed gate weights: row j = [Wih[j] | Whh[j]]
__device__ float g_bg[512];            // bih + bhh
__device__ float g_WxT[A_*256];        // transposed W_x: [a][k]
__device__ float g_dec[B_*A_];         // dec_fea, single buffer
__device__ float g_Sp2[2][B_*CH_];     // parity-buffered softmax partials
__device__ float g_CTp2[2][B_*CH_*DK_]; // parity-buffered context partials
__device__ float g_clp[NB_];           // per-block closs partials (deterministic)
// per-batch counters, each on its own 128B line
__device__ unsigned g_readyAB[B_*32];  // AB steps completed for batch b
__device__ unsigned g_SpCnt[B_*32];    // C partials count (16/step, monotonic)
__device__ unsigned g_done;

__device__ __forceinline__ float tanh_fast(float x) {
    float y; asm("tanh.approx.f32 %0, %1;" : "=f"(y) : "f"(x)); return y;
}
__device__ __forceinline__ float sigmoid_f(float x) {
    return 1.0f / (1.0f + __expf(-x));
}
__device__ __forceinline__ unsigned h2_to_u(__half2 h) {
    return *reinterpret_cast<unsigned*>(&h);
}
__device__ __forceinline__ float2 u_to_f2(unsigned u) {
    __half2 h = *reinterpret_cast<__half2*>(&u);
    return __half22float2(h);
}

// block-wide wait: tid0 spins until *c >= tgt, then acquire + syncthreads
__device__ __forceinline__ void waitc(volatile unsigned* c, unsigned tgt) {
    if (threadIdx.x == 0) {
        int sp = 0;
        while (*c < tgt) { if (++sp > 2048) __nanosleep(64); }
        __threadfence();
    }
    __syncthreads();
}
// block-wide signal: release writes, tid0 bumps counter
__device__ __forceinline__ void signalc(unsigned* c) {
    __threadfence();
    __syncthreads();
    if (threadIdx.x == 0) atomicAdd(c, 1u);
}

// ---------------- one-time: zfea GEMM + weight packing + counter reset -----
// grid 2048 x 256
__global__ void zfea_kernel(const float* __restrict__ z, const float* __restrict__ Wz,
                            const float* __restrict__ battn,
                            const float* __restrict__ Wih, const float* __restrict__ Whh,
                            const float* __restrict__ bih, const float* __restrict__ bhh,
                            const float* __restrict__ Wx) {
    int t = threadIdx.x;
    int bid = blockIdx.x;

    if (bid == 0) {
        if (t < B_) { g_readyAB[t*32] = 0; g_SpCnt[t*32] = 0; }
        if (t == 0) g_done = 0;
    }
    if (bid < 512) {                      // pack gate weights: row j = bid
        int j = bid;
        g_Wg[j*256 + t] = (t < 128) ? Wih[j*128 + t] : Whh[j*128 + (t-128)];
        if (t == 0) g_bg[j] = bih[j] + bhh[j];
    } else if (bid < 640) {               // W_x transpose: 32768 elems
        int i = (bid - 512)*256 + t;
        int a = i >> 8, k = i & 255;
        g_WxT[i] = Wx[k*A_ + a];
    }

    __shared__ float zs[64*DK_];
    int rowBase = bid * 64;
    const float* zsrc = z + (size_t)rowBase * DK_;
    #pragma unroll
    for (int k = 0; k < 32; k++) zs[t + k*256] = zsrc[t + k*256];
    __syncthreads();

    int tx = t & 31, ty = t >> 5;
    float acc[8][4];
    #pragma unroll
    for (int i = 0; i < 8; i++)
        #pragma unroll
        for (int c = 0; c < 4; c++) acc[i][c] = 0.0f;

    const float4* Wz4 = (const float4*)Wz;
    #pragma unroll 4
    for (int d = 0; d < DK_; d++) {
        float4 w = __ldg(&Wz4[d*32 + tx]);
        #pragma unroll
        for (int i = 0; i < 8; i++) {
            float zv = zs[(ty + 8*i)*DK_ + d];
            acc[i][0] = fmaf(zv, w.x, acc[i][0]);
            acc[i][1] = fmaf(zv, w.y, acc[i][1]);
            acc[i][2] = fmaf(zv, w.z, acc[i][2]);
            acc[i][3] = fmaf(zv, w.w, acc[i][3]);
        }
    }
    float4 bb = __ldg(&((const float4*)battn)[tx]);
    uint4* outp = (uint4*)g_zi;
    #pragma unroll
    for (int i = 0; i < 8; i++) {
        size_t r = rowBase + ty + 8*i;
        int lr = ty + 8*i;
        __half2 f0 = __floats2half2_rn(acc[i][0] + bb.x, acc[i][1] + bb.y);
        __half2 f1 = __floats2half2_rn(acc[i][2] + bb.z, acc[i][3] + bb.w);
        __half2 z0 = __floats2half2_rn(zs[lr*DK_ + tx*4],     zs[lr*DK_ + tx*4 + 1]);
        __half2 z1 = __floats2half2_rn(zs[lr*DK_ + tx*4 + 2], zs[lr*DK_ + tx*4 + 3]);
        uint4 pk;
        pk.x = h2_to_u(f0); pk.y = h2_to_u(f1);
        pk.z = h2_to_u(z0); pk.w = h2_to_u(z1);
        outp[r*32 + tx] = pk;
    }
}

// ---------------- persistent: batch-pair interleaved pipelines --------------
// bid 0..255: CD blocks (pair = bid>>4, seg = bid&15; batches 2p, 2p+1)
// bid 256..287: AB blocks (batch = bid-256): context assembly + LSTM + dec
__global__ __launch_bounds__(256, 2) void persistent_kernel(
        float* __restrict__ out, int T, int out_size,
        const float* __restrict__ mask,
        const float* __restrict__ wc, const float* __restrict__ v,
        const float* __restrict__ h0, const float* __restrict__ c0) {
    int bid = blockIdx.x;
    int tid = threadIdx.x;
    int warp = tid >> 5, lane = tid & 31;
    float closs_acc = 0.0f;
    size_t OUT_ATT = (size_t)B_ * T * DK_;

    if (bid >= 256) {
        // ==================== AB pipeline (one block per batch) ====================
        int b = bid - 256;
        __shared__ float xs[256];     // [s | h]
        __shared__ float hc[256];     // persistent h[0..127], c[128..255]
        __shared__ float gates[512];
        __shared__ float xh[256];     // [h_new | c_new]
        __shared__ float sp_s[CH_];

        if (tid < 128) hc[tid] = h0[b*H_ + tid];
        else           hc[tid] = c0[b*H_ + (tid - 128)];
        __syncthreads();

        const float4* Wg4  = (const float4*)g_Wg;
        const float4* WxT4 = (const float4*)g_WxT;

        for (int t = 0; t < T; t++) {
            // ---- context assembly: s(t-1) = sum_ch CTp / S ----
            if (t > 0) {
                int hb1 = (t - 1) & 1;
                waitc(&g_SpCnt[b*32], (unsigned)(16*t));
                if (tid < CH_) sp_s[tid] = g_Sp2[hb1][b*CH_ + tid];
                __syncthreads();
                if (tid < 128) {
                    float S = 0.0f;
                    #pragma unroll
                    for (int ch = 0; ch < CH_; ch++) S += sp_s[ch];
                    float invS = 1.0f / S;
                    float ctv = 0.0f;
                    #pragma unroll
                    for (int ch = 0; ch < CH_; ch++)
                        ctv += g_CTp2[hb1][(b*CH_ + ch)*DK_ + tid];
                    ctv *= invS;
                    xs[tid] = ctv;
                    out[(size_t)(b*T + (t-1))*DK_ + tid] = ctv;  // text output
                }
            } else {
                if (tid < 128) xs[tid] = 0.0f;
            }
            if (tid >= 128) xs[tid] = hc[tid - 128];
            __syncthreads();

            float4 xa = ((const float4*)xs)[lane*2];
            float4 xb = ((const float4*)xs)[lane*2 + 1];
            // gates: warp w -> j = w*64 .. w*64+63
            #pragma unroll 8
            for (int i = 0; i < 64; i++) {
                int j = warp*64 + i;
                float4 w0 = __ldg(&Wg4[j*64 + lane*2]);
                float4 w1 = __ldg(&Wg4[j*64 + lane*2 + 1]);
                float acc = w0.x*xa.x + w0.y*xa.y + w0.z*xa.z + w0.w*xa.w
                          + w1.x*xb.x + w1.y*xb.y + w1.z*xb.z + w1.w*xb.w;
                #pragma unroll
                for (int off = 16; off > 0; off >>= 1)
                    acc += __shfl_xor_sync(0xffffffffu, acc, off);
                if (lane == 0) gates[j] = acc + g_bg[j];
            }
            __syncthreads();
            if (tid < 128) {
                int j = tid;
                float cn = sigmoid_f(gates[H_ + j]) * hc[128 + j]
                         + sigmoid_f(gates[j]) * tanhf(gates[2*H_ + j]);
                float hn = sigmoid_f(gates[3*H_ + j]) * tanhf(cn);
                hc[j] = hn; hc[128 + j] = cn;
                xh[j] = hn; xh[128 + j] = cn;
            }
            __syncthreads();
            // dec: warp w -> a = w*16 .. w*16+15
            float4 ya = ((const float4*)xh)[lane*2];
            float4 yb = ((const float4*)xh)[lane*2 + 1];
            #pragma unroll 4
            for (int i = 0; i < 16; i++) {
                int a = warp*16 + i;
                float4 w0 = __ldg(&WxT4[a*64 + lane*2]);
                float4 w1 = __ldg(&WxT4[a*64 + lane*2 + 1]);
                float acc = w0.x*ya.x + w0.y*ya.y + w0.z*ya.z + w0.w*ya.w
                          + w1.x*yb.x + w1.y*yb.y + w1.z*yb.z + w1.w*yb.w;
                #pragma unroll
                for (int off = 16; off > 0; off >>= 1)
                    acc += __shfl_xor_sync(0xffffffffu, acc, off);
                if (lane == 0) g_dec[b*A_ + a] = acc;
            }
            signalc(&g_readyAB[b*32]);
        }
        // final step's text output
        {
            int hb1 = (T - 1) & 1;
            waitc(&g_SpCnt[b*32], (unsigned)(16*T));
            if (tid < CH_) sp_s[tid] = g_Sp2[hb1][b*CH_ + tid];
            __syncthreads();
            if (tid < 128) {
                float S = 0.0f;
                #pragma unroll
                for (int ch = 0; ch < CH_; ch++) S += sp_s[ch];
                float invS = 1.0f / S;
                float ctv = 0.0f;
                #pragma unroll
                for (int ch = 0; ch < CH_; ch++)
                    ctv += g_CTp2[hb1][(b*CH_ + ch)*DK_ + tid];
                out[(size_t)(b*T + (T-1))*DK_ + tid] = ctv * invS;
            }
        }
    } else {
        // ============ CD pipeline: one block serves batches {2p, 2p+1} ============
        int pair = bid >> 4, seg = bid & 15;
        int bs0 = pair*2, bs1 = pair*2 + 1;
        __shared__ float shm[136];

        float cov_r[2] = {0.0f, 0.0f};
        float p_r[2]   = {0.0f, 0.0f};
        float m_r[2];
        m_r[0] = __ldg(&mask[bs0*N_ + seg*256 + tid]);
        m_r[1] = __ldg(&mask[bs1*N_ + seg*256 + tid]);
        float4 wc4  = __ldg(&((const float4*)wc)[lane]);
        float4 v4   = __ldg(&((const float4*)v)[lane]);
        const uint4* zi4 = (const uint4*)g_zi;
        int n0 = seg * TILE_ + warp * 32;

        for (int t = 0; t < T; t++) {
            int hb = t & 1;

            // ---- Phase C for both batches (interleaved waits) ----
            #pragma unroll
            for (int u = 0; u < 2; u++) {
                int b = u ? bs1 : bs0;
                waitc(&g_readyAB[b*32], (unsigned)(t + 1));

                float4 dec4 = *(const float4*)&g_dec[b*A_ + lane*4];
                float4 ct = make_float4(0.f, 0.f, 0.f, 0.f);
                float Sacc = 0.0f;

                #pragma unroll 4
                for (int r = 0; r < 32; r++) {
                    size_t idx = (size_t)b*N_ + n0 + r;
                    float cov = __shfl_sync(0xffffffffu, cov_r[u], r);
                    float m   = __shfl_sync(0xffffffffu, m_r[u], r);
                    uint4 raw = zi4[idx*32 + lane];   // one LDG.128: {zf x4, z x4}
                    float2 fa = u_to_f2(raw.x);
                    float2 fb = u_to_f2(raw.y);
                    float t0 = tanh_fast(fmaf(cov, wc4.x, fa.x) + dec4.x);
                    float t1 = tanh_fast(fmaf(cov, wc4.y, fa.y) + dec4.y);
                    float t2 = tanh_fast(fmaf(cov, wc4.z, fb.x) + dec4.z);
                    float t3 = tanh_fast(fmaf(cov, wc4.w, fb.y) + dec4.w);
                    float e = v4.x*t0 + v4.y*t1 + v4.z*t2 + v4.w*t3;
                    #pragma unroll
                    for (int off = 16; off > 0; off >>= 1)
                        e += __shfl_xor_sync(0xffffffffu, e, off);
                    // e bounded by ||v||_1 (~9): exp cannot overflow, no global max
                    float p = (m > 0.0f) ? __expf(e) : 0.0f;
                    float2 za = u_to_f2(raw.z);
                    float2 zb = u_to_f2(raw.w);
                    ct.x = fmaf(p, za.x, ct.x);
                    ct.y = fmaf(p, za.y, ct.y);
                    ct.z = fmaf(p, zb.x, ct.z);
                    ct.w = fmaf(p, zb.y, ct.w);
                    if (lane == r) p_r[u] = p;
                    Sacc += p;
                }

                if (tid < DK_) shm[tid] = 0.0f;
                if (lane == 0) shm[128 + warp] = Sacc;
                __syncthreads();
                atomicAdd(&shm[lane*4 + 0], ct.x);
                atomicAdd(&shm[lane*4 + 1], ct.y);
                atomicAdd(&shm[lane*4 + 2], ct.z);
                atomicAdd(&shm[lane*4 + 3], ct.w);
                __syncthreads();
                if (tid < DK_)
                    g_CTp2[hb][(b*CH_ + seg)*DK_ + tid] = shm[tid];
                if (tid == 0) {
                    float S = 0.0f;
                    #pragma unroll
                    for (int w = 0; w < 8; w++) S += shm[128 + w];
                    g_Sp2[hb][b*CH_ + seg] = S;
                }
                signalc(&g_SpCnt[b*32]);
            }

            // ---- D-lite for both batches ----
            #pragma unroll
            for (int u = 0; u < 2; u++) {
                int b = u ? bs1 : bs0;
                waitc(&g_SpCnt[b*32], (unsigned)(16*(t + 1)));
                if (tid < CH_) shm[tid] = g_Sp2[hb][b*CH_ + tid];
                __syncthreads();
                float S = 0.0f;
                #pragma unroll
                for (int ch = 0; ch < CH_; ch++) S += shm[ch];
                float invS = 1.0f / S;

                int n = seg*256 + tid;
                float attn = p_r[u] * invS;
                float cl = fminf(attn, cov_r[u]);   // coverage BEFORE update
                cov_r[u] += attn;
                out[OUT_ATT + (size_t)(b*T + t)*N_ + n] = attn;

                #pragma unroll
                for (int off = 16; off > 0; off >>= 1)
                    cl += __shfl_xor_sync(0xffffffffu, cl, off);
                __syncthreads();
                if (lane == 0) shm[16 + warp] = cl;
                __syncthreads();
                if (tid == 0) {
                    float s = 0.0f;
                    #pragma unroll
                    for (int w = 0; w < 8; w++) s += shm[16 + w];
                    closs_acc += s;
                }
                __syncthreads();
            }
        }
    }

    // deterministic closs: ordered reduction of per-block partials
    if (tid == 0) g_clp[bid] = closs_acc;
    __threadfence();
    __syncthreads();
    if (tid == 0) atomicAdd(&g_done, 1u);
    if (bid == 0 && tid == 0) {
        volatile unsigned* d = &g_done;
        while (*d < NB_) __nanosleep(128);
        __threadfence();
        float s = 0.0f;
        for (int i = 0; i < NB_; i++) s += g_clp[i];
        out[out_size - 1] = s / (float)B_;
    }
}

// ---------------- host driver ----------------------------------------------
extern "C" void kernel_launch(void* const* d_in, const int* in_sizes, int n_in,
                              void* d_out, int out_size) {
    const float* z     = (const float*)d_in[0];
    const float* mask  = (const float*)d_in[1];
    const float* h0    = (const float*)d_in[2];
    const float* c0    = (const float*)d_in[3];
    const float* W_ih  = (const float*)d_in[4];
    const float* W_hh  = (const float*)d_in[5];
    const float* b_ih  = (const float*)d_in[6];
    const float* b_hh  = (const float*)d_in[7];
    const float* W_x   = (const float*)d_in[8];
    const float* W_z   = (const float*)d_in[9];
    const float* w_c   = (const float*)d_in[10];
    const float* b_attn= (const float*)d_in[11];
    const float* v     = (const float*)d_in[12];
    float* out = (float*)d_out;

    int T = (out_size - 1) / (B_ * (DK_ + N_));

    zfea_kernel<<<(B_*N_)/64, 256>>>(z, W_z, b_attn, W_ih, W_hh, b_ih, b_hh, W_x);
    persistent_kernel<<<NB_, 256>>>(out, T, out_size, mask, w_c, v, h0, c0);
}